// round 10
// baseline (speedup 1.0000x reference)
#include <cuda_runtime.h>

#define NUPD   16
#define NMO    64
#define NCONF  64
#define NBATCH 4096
#define NELEC  32
#define RS     65   // padded shared row stride (floats)

__device__ __forceinline__ float fast_rcp(float x) {
    float r;
    asm("rcp.approx.f32 %0, %1;" : "=f"(r) : "f"(x));
    return r * (2.0f - x * r);   // one Newton step -> ~1 ulp
}

__global__ void __launch_bounds__(256, 2) kinetic_kernel(
    const float* __restrict__ MO,
    const float* __restrict__ d2MO,
    const float* __restrict__ dJdMO,
    const float* __restrict__ d2JMO,
    const int*   __restrict__ cup,
    const int*   __restrict__ cdown,
    float*       __restrict__ out)   // [kinetic (B,NCONF) | det_prod (B,NCONF)]
{
    __shared__ float sM[NELEC * RS];
    __shared__ float sB[NELEC * RS];
    __shared__ int   sCfg[2 * NCONF * NUPD];

    const int b   = blockIdx.x;
    const int tid = threadIdx.x;

    // ---- stage configs ----
    for (int i = tid; i < NCONF * NUPD; i += 256) {
        sCfg[i]                = cup[i];
        sCfg[NCONF * NUPD + i] = cdown[i];
    }

    // ---- stage MO rows + fused B = d2MO + 2*dJdMO + d2JMO ----
    const size_t base = (size_t)b * (NELEC * NMO);
    const float4* gM = (const float4*)(MO    + base);
    const float4* gX = (const float4*)(d2MO  + base);
    const float4* gY = (const float4*)(dJdMO + base);
    const float4* gZ = (const float4*)(d2JMO + base);
    #pragma unroll
    for (int r = 0; r < 2; ++r) {
        int i   = tid + r * 256;
        int row = i >> 4;
        int c4  = i & 15;
        float4 m = gM[i], x = gX[i], w = gY[i], z4 = gZ[i];
        float* pm = &sM[row * RS + c4 * 4];
        pm[0] = m.x; pm[1] = m.y; pm[2] = m.z; pm[3] = m.w;
        float* pb = &sB[row * RS + c4 * 4];
        pb[0] = x.x + 2.0f * w.x + z4.x;
        pb[1] = x.y + 2.0f * w.y + z4.y;
        pb[2] = x.z + 2.0f * w.z + z4.z;
        pb[3] = x.w + 2.0f * w.w + z4.w;
    }
    __syncthreads();

    // ---- layout: 4 eight-lane segments per warp, one 16x16 system each
    //      (2 rows per lane). Segs (0,1)=(up,down) of one config, (2,3) of another.
    const int lane = tid & 31;
    const int warp = tid >> 5;
    const int q    = lane & 7;          // lane within segment
    const int seg  = lane >> 3;         // 0..3
    const int spin = seg & 1;
    const int sub  = seg >> 1;
    const unsigned FULL = 0xFFFFFFFFu;
    const unsigned segmask = 0xFFu << (seg * 8);

    const float* rM0   = &sM[(spin * NUPD + q) * RS];   // my row q
    const float* rM1   = rM0 + 8 * RS;                  // my row q+8
    const float* bRows = &sB[(spin * NUPD) * RS];
    const int*   myCfg = &sCfg[spin * (NCONF * NUPD)];

    #pragma unroll 1
    for (int it = 0; it < 4; ++it) {
        const int c = (warp + it * 8) * 2 + sub;

        // gather my two rows of A
        float a0[16], a1[16];
        #pragma unroll
        for (int j = 0; j < 16; ++j) {
            int cj = myCfg[c * NUPD + j];
            a0[j] = rM0[cj];
            a1[j] = rM1[cj];
        }

        // ---- Gauss-Jordan on A, transform tracked in pivot-step coords ----
        float z0[16], z1[16];
        int   piv0 = -1, piv1 = -1;
        int   virt0 = q, virt1 = q + 8;
        float det = 1.0f, rd0 = 1.0f, rd1 = 1.0f;
        bool  neg = false;
        unsigned permLo = 0u, permHi = 0u;   // nibble s -> pivot ROW of step s

        #pragma unroll
        for (int s = 0; s < 16; ++s) {
            // pivot: max |a[s]| over both local slots; pack slot(bit3)+lane(0..2)
            unsigned k0 = (piv0 < 0)
                ? ((__float_as_uint(fabsf(a0[s])) & 0xFFFFFFF0u) | (unsigned)q) : 0u;
            unsigned k1 = (piv1 < 0)
                ? ((__float_as_uint(fabsf(a1[s])) & 0xFFFFFFF0u) | 8u | (unsigned)q) : 0u;
            unsigned cu  = k0 > k1 ? k0 : k1;
            unsigned key = __reduce_max_sync(segmask, cu);
            int  bl = key & 7;
            bool sl = (key >> 3) & 1;

            float pv = __shfl_sync(FULL, sl ? a1[s]  : a0[s],  bl, 8);
            int   vb = __shfl_sync(FULL, sl ? virt1  : virt0,  bl, 8);
            neg ^= (vb != s);
            bool isSrc = (q == bl);
            bool isp0 = isSrc && !sl;
            bool isp1 = isSrc &&  sl;
            if (virt0 == s) virt0 = vb;
            if (virt1 == s) virt1 = vb;
            if (isp0) virt0 = s;
            if (isp1) virt1 = s;

            det *= pv;
            float rpv = fast_rcp(pv);
            if (isp0) { piv0 = s; rd0 = rpv; }
            if (isp1) { piv1 = s; rd1 = rpv; }
            unsigned pr = (unsigned)(bl | (sl ? 8 : 0));   // uniform in segment
            if (s < 8) permLo |= pr << (4 * s);
            else       permHi |= pr << (4 * (s - 8));

            float m0 = isp0 ? 0.0f : a0[s] * rpv;
            float m1 = isp1 ? 0.0f : a1[s] * rpv;

            #pragma unroll
            for (int j = s + 1; j < 16; ++j) {
                float pj = __shfl_sync(FULL, sl ? a1[j] : a0[j], bl, 8);
                a0[j] -= m0 * pj;
                a1[j] -= m1 * pj;
            }
            #pragma unroll
            for (int t = 0; t < 16; ++t)
                if (t < s) {
                    float zt = __shfl_sync(FULL, sl ? z1[t] : z0[t], bl, 8);
                    z0[t] -= m0 * zt;
                    z1[t] -= m1 * zt;
                }
            z0[s] = (isp0 ? 1.0f : 0.0f) - m0;
            z1[s] = (isp1 ? 1.0f : 0.0f) - m1;
        }

        // ---- trace: each slot contributes rdiag * sum_t z[t]*B[p_t][col] ----
        const int col0 = myCfg[c * NUPD + piv0];
        const int col1 = myCfg[c * NUPD + piv1];
        float acc0 = 0.0f, acc1 = 0.0f;
        #pragma unroll
        for (int t = 0; t < 16; ++t) {
            int pt = (int)((t < 8 ? (permLo >> (4 * t))
                                  : (permHi >> (4 * (t - 8)))) & 15u);
            const float* brow = &bRows[pt * RS];
            acc0 += z0[t] * brow[col0];
            acc1 += z1[t] * brow[col1];
        }
        float t8 = acc0 * rd0 + acc1 * rd1;

        // ---- reduce trace within 8-lane segment, combine spins ----
        float tr = t8;
        tr += __shfl_xor_sync(FULL, tr, 4, 8);
        tr += __shfl_xor_sync(FULL, tr, 2, 8);
        tr += __shfl_xor_sync(FULL, tr, 1, 8);
        float sdet = neg ? -det : det;

        float tro  = __shfl_xor_sync(FULL, tr,   8, 16);   // other spin
        float deto = __shfl_xor_sync(FULL, sdet, 8, 16);
        float dp   = sdet * deto;
        float kin  = -0.5f * (tr + tro) * dp;

        if ((lane & 15) == 0) {
            out[(size_t)b * NCONF + c] = kin;
            out[(size_t)(NBATCH * NCONF) + (size_t)b * NCONF + c] = dp;
        }
    }
}

extern "C" void kernel_launch(void* const* d_in, const int* in_sizes, int n_in,
                              void* d_out, int out_size) {
    (void)in_sizes; (void)n_in; (void)out_size;
    kinetic_kernel<<<NBATCH, 256>>>(
        (const float*)d_in[0],   // MO
        (const float*)d_in[1],   // d2MO
        (const float*)d_in[2],   // dJdMO
        (const float*)d_in[3],   // d2JMO
        (const int*)  d_in[4],   // cup
        (const int*)  d_in[5],   // cdown
        (float*)d_out);
}

// round 11
// speedup vs baseline: 1.9103x; 1.9103x over previous
#include <cuda_runtime.h>

#define NUPD   16
#define NMO    64
#define NCONF  64
#define NBATCH 4096
#define NELEC  32
#define RS     65   // padded shared row stride (floats)

__device__ __forceinline__ float fast_rcp(float x) {
    float r;
    asm("rcp.approx.f32 %0, %1;" : "=f"(r) : "f"(x));
    return r * (2.0f - x * r);   // one Newton step -> ~1 ulp
}

__global__ void __launch_bounds__(256) kinetic_kernel(
    const float* __restrict__ MO,
    const float* __restrict__ d2MO,
    const float* __restrict__ dJdMO,
    const float* __restrict__ d2JMO,
    const int*   __restrict__ cup,
    const int*   __restrict__ cdown,
    float*       __restrict__ out)   // [kinetic (B,NCONF) | det_prod (B,NCONF)]
{
    __shared__ float  sM[NELEC * RS];
    __shared__ float  sB[NELEC * RS];
    __shared__ int    sCfg[2 * NCONF * NUPD];
    // pivot-row broadcast scratch: [warp][buf][half][chunk]; halves 16 words
    // apart -> disjoint banks inside one warp-wide LDS.128 / STS.128.
    __shared__ float4 sScr[8][2][2][4];

    const int b   = blockIdx.x;
    const int tid = threadIdx.x;

    // ---- stage configs ----
    for (int i = tid; i < NCONF * NUPD; i += 256) {
        sCfg[i]                = cup[i];
        sCfg[NCONF * NUPD + i] = cdown[i];
    }

    // ---- stage MO rows + fused B = d2MO + 2*dJdMO + d2JMO ----
    const size_t base = (size_t)b * (NELEC * NMO);
    const float4* gM = (const float4*)(MO    + base);
    const float4* gX = (const float4*)(d2MO  + base);
    const float4* gY = (const float4*)(dJdMO + base);
    const float4* gZ = (const float4*)(d2JMO + base);
    #pragma unroll
    for (int r = 0; r < 2; ++r) {
        int i   = tid + r * 256;
        int row = i >> 4;
        int c4  = i & 15;
        float4 m = gM[i], x = gX[i], wv = gY[i], z4 = gZ[i];
        float* pm = &sM[row * RS + c4 * 4];
        pm[0] = m.x; pm[1] = m.y; pm[2] = m.z; pm[3] = m.w;
        float* pb = &sB[row * RS + c4 * 4];
        pb[0] = x.x + 2.0f * wv.x + z4.x;
        pb[1] = x.y + 2.0f * wv.y + z4.y;
        pb[2] = x.z + 2.0f * wv.z + z4.z;
        pb[3] = x.w + 2.0f * wv.w + z4.w;
    }
    __syncthreads();

    // ---- warp layout: 2 sixteen-lane groups per warp = (up, down) of one config ----
    const int lane = tid & 31;
    const int warp = tid >> 5;
    const int half = lane >> 4;         // 0: up, 1: down
    const int l    = lane & 15;         // my row of the 16x16 system
    const unsigned FULL = 0xFFFFFFFFu;
    const unsigned segmask = half ? 0xFFFF0000u : 0x0000FFFFu;

    const float* myM   = &sM[(half * NUPD + l) * RS];
    const float* bRows = &sB[(half * NUPD) * RS];
    const int*   myCfg = &sCfg[half * (NCONF * NUPD)];

    #pragma unroll 1
    for (int it = 0; it < 8; ++it) {
        const int c = warp + it * 8;

        // gather my row of A into the unified working array w.
        // Invariant at step s:  w[j] = a[j] for j>=s,  w[t] = z[t] for t<s.
        float w[16];
        #pragma unroll
        for (int j = 0; j < 16; ++j)
            w[j] = myM[myCfg[c * NUPD + j]];

        int   pivstep = -1;
        float det   = 1.0f;
        float rdiag = 1.0f;
        int   virt  = l;        // virtual row position (permutation parity)
        bool  neg   = false;
        unsigned permLo = 0u, permHi = 0u;   // nibble s -> pivot row of step s

        #pragma unroll
        for (int s = 0; s < 16; ++s) {
            // pivot: max |w[s]| among non-pivoted rows; lane id in low 4 bits
            unsigned cand = (pivstep < 0)
                ? ((__float_as_uint(fabsf(w[s])) & 0xFFFFFFF0u) | (unsigned)l)
                : 0u;
            unsigned key = __reduce_max_sync(segmask, cand);
            int  bl    = key & 15;               // uniform within group
            bool ispiv = (l == bl);

            // pivot lane publishes its ENTIRE w (uniform 16-float broadcast);
            // pv = w[s] rides along. Double-buffered -> one sync per step.
            float4* scr = &sScr[warp][s & 1][half][0];
            if (ispiv) {
                scr[0] = make_float4(w[0],  w[1],  w[2],  w[3]);
                scr[1] = make_float4(w[4],  w[5],  w[6],  w[7]);
                scr[2] = make_float4(w[8],  w[9],  w[10], w[11]);
                scr[3] = make_float4(w[12], w[13], w[14], w[15]);
            }
            __syncwarp();
            float4 q0 = scr[0], q1 = scr[1], q2 = scr[2], q3 = scr[3];
            int vb = __shfl_sync(FULL, virt, bl, 16);

            float p[16] = { q0.x, q0.y, q0.z, q0.w,
                            q1.x, q1.y, q1.z, q1.w,
                            q2.x, q2.y, q2.z, q2.w,
                            q3.x, q3.y, q3.z, q3.w };
            float pv = p[s];                     // compile-time index

            neg ^= (vb != s);
            if (virt == s) virt = vb;
            if (ispiv)     virt = s;

            det *= pv;
            float rpv = fast_rcp(pv);
            if (ispiv) { pivstep = s; rdiag = rpv; }
            if (s < 8) permLo |= (unsigned)bl << (4 * s);
            else       permHi |= (unsigned)bl << (4 * (s - 8));

            float m = ispiv ? 0.0f : w[s] * rpv;
            #pragma unroll
            for (int j = 0; j < 16; ++j)
                if (j != s)
                    w[j] -= m * p[j];
            w[s] = (ispiv ? 1.0f : 0.0f) - m;    // z[s] born in place of a[s]
        }

        // ---- trace: tr = sum_l rdiag_l * sum_t w[t] * B[p_t][pivstep_l] ----
        const int col = myCfg[c * NUPD + pivstep];
        float acc = 0.0f;
        #pragma unroll
        for (int t = 0; t < 16; ++t) {
            int pt = (int)((t < 8 ? (permLo >> (4 * t))
                                  : (permHi >> (4 * (t - 8)))) & 15u);
            acc += w[t] * bRows[pt * RS + col];
        }
        float tcontrib = acc * rdiag;

        // ---- reduce trace within group, combine spins across halves ----
        float tr = tcontrib;
        #pragma unroll
        for (int off = 8; off; off >>= 1)
            tr += __shfl_xor_sync(FULL, tr, off, 16);
        float sdet = neg ? -det : det;

        float tro  = __shfl_xor_sync(FULL, tr,   16);   // other spin
        float deto = __shfl_xor_sync(FULL, sdet, 16);
        float dp   = sdet * deto;
        float kin  = -0.5f * (tr + tro) * dp;

        if (lane == 0) {
            out[(size_t)b * NCONF + c] = kin;
            out[(size_t)(NBATCH * NCONF) + (size_t)b * NCONF + c] = dp;
        }
    }
}

extern "C" void kernel_launch(void* const* d_in, const int* in_sizes, int n_in,
                              void* d_out, int out_size) {
    (void)in_sizes; (void)n_in; (void)out_size;
    kinetic_kernel<<<NBATCH, 256>>>(
        (const float*)d_in[0],   // MO
        (const float*)d_in[1],   // d2MO
        (const float*)d_in[2],   // dJdMO
        (const float*)d_in[3],   // d2JMO
        (const int*)  d_in[4],   // cup
        (const int*)  d_in[5],   // cdown
        (float*)d_out);
}

// round 14
// speedup vs baseline: 1.9394x; 1.0152x over previous
#include <cuda_runtime.h>

#define NUPD   16
#define NMO    64
#define NCONF  64
#define NBATCH 4096
#define NELEC  32
#define RS     65   // padded shared row stride (floats)
#define SEGW   20   // padded scratch stride per segment (floats, 16B-aligned)

__device__ __forceinline__ float fast_rcp(float x) {
    float r;
    asm("rcp.approx.f32 %0, %1;" : "=f"(r) : "f"(x));
    return r * (2.0f - x * r);   // one Newton step -> ~1 ulp
}

__global__ void __launch_bounds__(256) kinetic_kernel(
    const float* __restrict__ MO,
    const float* __restrict__ d2MO,
    const float* __restrict__ dJdMO,
    const float* __restrict__ d2JMO,
    const int*   __restrict__ cup,
    const int*   __restrict__ cdown,
    float*       __restrict__ out)   // [kinetic (B,NCONF) | det_prod (B,NCONF)]
{
    __shared__ float sM[NELEC * RS];
    __shared__ float sB[NELEC * RS];
    __shared__ int   sCfg[2 * NCONF * NUPD];
    // pivot-row scratch: [warp][buf][seg][SEGW]
    __shared__ float sScr[8 * 2 * 4 * SEGW];

    const int b   = blockIdx.x;
    const int tid = threadIdx.x;

    for (int i = tid; i < NCONF * NUPD; i += 256) {
        sCfg[i]                = cup[i];
        sCfg[NCONF * NUPD + i] = cdown[i];
    }

    const size_t base = (size_t)b * (NELEC * NMO);
    const float4* gM = (const float4*)(MO    + base);
    const float4* gX = (const float4*)(d2MO  + base);
    const float4* gY = (const float4*)(dJdMO + base);
    const float4* gZ = (const float4*)(d2JMO + base);
    #pragma unroll
    for (int r = 0; r < 2; ++r) {
        int i   = tid + r * 256;
        int row = i >> 4;
        int c4  = i & 15;
        float4 m = gM[i], x = gX[i], wv = gY[i], z4 = gZ[i];
        float* pm = &sM[row * RS + c4 * 4];
        pm[0] = m.x; pm[1] = m.y; pm[2] = m.z; pm[3] = m.w;
        float* pb = &sB[row * RS + c4 * 4];
        pb[0] = x.x + 2.0f * wv.x + z4.x;
        pb[1] = x.y + 2.0f * wv.y + z4.y;
        pb[2] = x.z + 2.0f * wv.z + z4.z;
        pb[3] = x.w + 2.0f * wv.w + z4.w;
    }
    __syncthreads();

    // ---- 4 eight-lane segments per warp; each = one 16x16 system, 2 rows/lane.
    //      segs (0,1) = (up,down) of config 2p ; segs (2,3) of config 2p+1.
    const int lane = tid & 31;
    const int warp = tid >> 5;
    const int q    = lane & 7;
    const int seg  = lane >> 3;
    const int spin = seg & 1;
    const int sub  = seg >> 1;
    const unsigned FULL = 0xFFFFFFFFu;
    const unsigned segmask = 0xFFu << (seg * 8);

    const float* rM0   = &sM[(spin * NUPD + q) * RS];   // my row q
    const float* rM1   = rM0 + 8 * RS;                  // my row q+8
    const float* bRows = &sB[(spin * NUPD) * RS];
    const int*   myCfg = &sCfg[spin * (NCONF * NUPD)];

    #pragma unroll 1
    for (int it = 0; it < 4; ++it) {
        const int c = (warp + it * 8) * 2 + sub;

        // unified working arrays: w[j]=a[j] for j>=s, w[t]=z[t] for t<s
        float w0[16], w1[16];
        #pragma unroll
        for (int j = 0; j < 16; ++j) {
            int cj = myCfg[c * NUPD + j];
            w0[j] = rM0[cj];
            w1[j] = rM1[cj];
        }

        int   piv0 = -1, piv1 = -1;
        int   virt0 = q, virt1 = q + 8;
        float det = 1.0f, rd0 = 1.0f, rd1 = 1.0f;
        bool  neg = false;
        unsigned permLo = 0u, permHi = 0u;   // nibble s -> pivot row of step s

        #pragma unroll
        for (int s = 0; s < 16; ++s) {
            // pivot: max |w[s]| over both slots; key low bits = slot<<3 | lane
            unsigned k0 = (piv0 < 0)
                ? ((__float_as_uint(fabsf(w0[s])) & 0xFFFFFFF0u) | (unsigned)q) : 0u;
            unsigned k1 = (piv1 < 0)
                ? ((__float_as_uint(fabsf(w1[s])) & 0xFFFFFFF0u) | 8u | (unsigned)q) : 0u;
            unsigned cu  = k0 > k1 ? k0 : k1;
            unsigned key = __reduce_max_sync(segmask, cu);
            int  bl = key & 7;
            bool sl = (key & 8u) != 0u;
            bool isp0 = (q == bl) && !sl;
            bool isp1 = (q == bl) &&  sl;

            // pivot slot publishes its whole w (static branch, no selects)
            float4* scr = (float4*)&sScr[(((warp << 1) | (s & 1)) * 4 + seg) * SEGW];
            if (isp0) {
                scr[0] = make_float4(w0[0],  w0[1],  w0[2],  w0[3]);
                scr[1] = make_float4(w0[4],  w0[5],  w0[6],  w0[7]);
                scr[2] = make_float4(w0[8],  w0[9],  w0[10], w0[11]);
                scr[3] = make_float4(w0[12], w0[13], w0[14], w0[15]);
            }
            if (isp1) {
                scr[0] = make_float4(w1[0],  w1[1],  w1[2],  w1[3]);
                scr[1] = make_float4(w1[4],  w1[5],  w1[6],  w1[7]);
                scr[2] = make_float4(w1[8],  w1[9],  w1[10], w1[11]);
                scr[3] = make_float4(w1[12], w1[13], w1[14], w1[15]);
            }
            __syncwarp();

            int vb = __shfl_sync(FULL, sl ? virt1 : virt0, bl, 8);
            neg ^= (vb != s);
            if (virt0 == s) virt0 = vb;
            if (virt1 == s) virt1 = vb;
            if (isp0) virt0 = s;
            if (isp1) virt1 = s;

            const int cs = s >> 2;           // chunk holding column s
            float4 qs = scr[cs];
            float pv = (s & 3) == 0 ? qs.x : (s & 3) == 1 ? qs.y
                     : (s & 3) == 2 ? qs.z : qs.w;

            det *= pv;
            float rpv = fast_rcp(pv);
            float m0 = isp0 ? 0.0f : w0[s] * rpv;
            float m1 = isp1 ? 0.0f : w1[s] * rpv;
            if (isp0) { piv0 = s; rd0 = rpv; }
            if (isp1) { piv1 = s; rd1 = rpv; }
            unsigned pr = (unsigned)(bl | (sl ? 8 : 0));   // pivot ROW (uniform)
            if (s < 8) permLo |= pr << (4 * s);
            else       permHi |= pr << (4 * (s - 8));

            #pragma unroll
            for (int ci = 0; ci < 4; ++ci) {
                float4 qq = (ci == cs) ? qs : scr[ci];
                float qa[4] = { qq.x, qq.y, qq.z, qq.w };
                #pragma unroll
                for (int e = 0; e < 4; ++e) {
                    int j = ci * 4 + e;
                    if (j != s) {
                        w0[j] -= m0 * qa[e];
                        w1[j] -= m1 * qa[e];
                    }
                }
            }
            w0[s] = (isp0 ? 1.0f : 0.0f) - m0;   // z[s] born in place of a[s]
            w1[s] = (isp1 ? 1.0f : 0.0f) - m1;
        }

        // ---- trace: each slot adds rdiag * sum_t w[t] * B[p_t][col] ----
        const int col0 = myCfg[c * NUPD + piv0];
        const int col1 = myCfg[c * NUPD + piv1];
        float acc0 = 0.0f, acc1 = 0.0f;
        #pragma unroll
        for (int t = 0; t < 16; ++t) {
            int pt = (int)((t < 8 ? (permLo >> (4 * t))
                                  : (permHi >> (4 * (t - 8)))) & 15u);
            const float* brow = &bRows[pt * RS];
            acc0 += w0[t] * brow[col0];
            acc1 += w1[t] * brow[col1];
        }
        float t8 = acc0 * rd0 + acc1 * rd1;

        // ---- reduce trace in segment, combine spins across seg pairs ----
        float tr = t8;
        tr += __shfl_xor_sync(FULL, tr, 4, 8);
        tr += __shfl_xor_sync(FULL, tr, 2, 8);
        tr += __shfl_xor_sync(FULL, tr, 1, 8);
        float sdet = neg ? -det : det;

        float tro  = __shfl_xor_sync(FULL, tr,   8, 16);
        float deto = __shfl_xor_sync(FULL, sdet, 8, 16);
        float dp   = sdet * deto;
        float kin  = -0.5f * (tr + tro) * dp;

        if ((lane & 15) == 0) {
            out[(size_t)b * NCONF + c] = kin;
            out[(size_t)(NBATCH * NCONF) + (size_t)b * NCONF + c] = dp;
        }
    }
}

extern "C" void kernel_launch(void* const* d_in, const int* in_sizes, int n_in,
                              void* d_out, int out_size) {
    (void)in_sizes; (void)n_in; (void)out_size;
    kinetic_kernel<<<NBATCH, 256>>>(
        (const float*)d_in[0],   // MO
        (const float*)d_in[1],   // d2MO
        (const float*)d_in[2],   // dJdMO
        (const float*)d_in[3],   // d2JMO
        (const int*)  d_in[4],   // cup
        (const int*)  d_in[5],   // cdown
        (float*)d_out);
}